// round 5
// baseline (speedup 1.0000x reference)
#include <cuda_runtime.h>
#include <cstdint>
#include <cstddef>

#define BB 8
#define NN 8192
#define DD 3
#define CC 64
#define MM 2048
#define KK 32
#define CIN 67
#define HID 268
#define OUTD 128

__device__ int g_nbr[BB * MM * KK];

// ---------------------------------------------------------------------------
// Farthest point sampling: one block per batch, 1024 threads, all state in regs.
// Distance rounding replicated as XLA's fused square+reduce with FP contraction:
//   d = fma(dz,dz, fma(dy,dy, dx*dx))
// Tie-break: lowest index (matches jnp.argmax first-occurrence).
// ---------------------------------------------------------------------------
__global__ void fps_kernel(const float* __restrict__ x,
                           const int* __restrict__ first_idx,
                           float* __restrict__ centers) {
    constexpr int T = 1024;
    constexpr int PPT = NN / T; // 8
    int b = blockIdx.x;
    int t = threadIdx.x;
    int lane = t & 31, warp = t >> 5;
    const float* xb = x + (size_t)b * NN * 3;

    float px[PPT], py[PPT], pz[PPT], d[PPT];
#pragma unroll
    for (int s = 0; s < PPT; s++) {
        int n = t + T * s;
        px[s] = xb[n * 3 + 0];
        py[s] = xb[n * 3 + 1];
        pz[s] = xb[n * 3 + 2];
    }

    __shared__ float s_f[3];
    __shared__ unsigned long long s_red[32];
    __shared__ int s_far;

    if (t == 0) {
        int fi = first_idx[b];
        s_f[0] = xb[fi * 3 + 0];
        s_f[1] = xb[fi * 3 + 1];
        s_f[2] = xb[fi * 3 + 2];
    }
    __syncthreads();
    float fx = s_f[0], fy = s_f[1], fz = s_f[2];
    if (t == 0) {
        float* c = centers + (size_t)b * MM * 3;
        c[0] = fx; c[1] = fy; c[2] = fz;
    }
#pragma unroll
    for (int s = 0; s < PPT; s++) {
        float dx = __fsub_rn(px[s], fx);
        float dy = __fsub_rn(py[s], fy);
        float dz = __fsub_rn(pz[s], fz);
        d[s] = __fmaf_rn(dz, dz, __fmaf_rn(dy, dy, __fmul_rn(dx, dx)));
    }

    for (int it = 1; it < MM; it++) {
        // local argmax (first-index on ties: indices ascend with s, strict >)
        float bd = -1.0f;
        int bi = 0;
#pragma unroll
        for (int s = 0; s < PPT; s++) {
            if (d[s] > bd) { bd = d[s]; bi = t + T * s; }
        }
        unsigned long long key =
            ((unsigned long long)__float_as_uint(bd) << 32) |
            (unsigned)(0xFFFFFFFFu - (unsigned)bi);
#pragma unroll
        for (int o = 16; o; o >>= 1) {
            unsigned long long other = __shfl_xor_sync(0xffffffffu, key, o);
            if (other > key) key = other;
        }
        if (lane == 0) s_red[warp] = key;
        __syncthreads();
        if (warp == 0) {
            key = s_red[lane];
#pragma unroll
            for (int o = 16; o; o >>= 1) {
                unsigned long long other = __shfl_xor_sync(0xffffffffu, key, o);
                if (other > key) key = other;
            }
            if (lane == 0)
                s_far = (int)(0xFFFFFFFFu - (unsigned)(key & 0xFFFFFFFFu));
        }
        __syncthreads();
        int far = s_far;
        if ((far & (T - 1)) == t) {
            int s = far >> 10;
            s_f[0] = px[s]; s_f[1] = py[s]; s_f[2] = pz[s];
        }
        __syncthreads();
        fx = s_f[0]; fy = s_f[1]; fz = s_f[2];
        if (t == 0) {
            float* c = centers + ((size_t)b * MM + it) * 3;
            c[0] = fx; c[1] = fy; c[2] = fz;
        }
#pragma unroll
        for (int s = 0; s < PPT; s++) {
            float dx = __fsub_rn(px[s], fx);
            float dy = __fsub_rn(py[s], fy);
            float dz = __fsub_rn(pz[s], fz);
            float nd = __fmaf_rn(dz, dz, __fmaf_rn(dy, dy, __fmul_rn(dx, dx)));
            d[s] = fminf(d[s], nd);
        }
    }
}

// ---------------------------------------------------------------------------
// Ball query: 4 warps/block, 1 center/warp, x staged in shared in 2048-pt
// tiles. K=32 smallest d2 < r^2 maintained as one slot per lane
// (replace-current-max insertion, stable w.r.t. index order like jnp.argsort).
// Unfilled slots -> index NN-1 (JAX -1 wrap). Same FMA-contracted distance.
// ---------------------------------------------------------------------------
__global__ void bq_kernel(const float* __restrict__ x,
                          const float* __restrict__ centers,
                          int* __restrict__ nbr) {
    constexpr int WPB = 4;
    constexpr int TILE = 2048;
    __shared__ float sx[TILE * 3];

    int w = threadIdx.x >> 5;
    int lane = threadIdx.x & 31;
    int cid = blockIdx.x * WPB + w;
    int b = cid >> 11; // / MM
    const float* xb = x + (size_t)b * NN * 3;

    float cx, cy, cz;
    {
        const float* c = centers + (size_t)cid * 3;
        cx = c[0]; cy = c[1]; cz = c[2];
    }
    const float r2 = 0.09f;
    float sd2 = __int_as_float(0x7f800000); // +inf
    int sidx = NN - 1;

    for (int tile = 0; tile < NN / TILE; tile++) {
        __syncthreads();
        const float4* src = (const float4*)(xb + tile * TILE * 3);
        for (int i = threadIdx.x; i < TILE * 3 / 4; i += WPB * 32)
            ((float4*)sx)[i] = src[i];
        __syncthreads();
        int base = tile * TILE;
        for (int i0 = 0; i0 < TILE; i0 += 32) {
            int i = i0 + lane;
            float dx = __fsub_rn(sx[3 * i + 0], cx);
            float dy = __fsub_rn(sx[3 * i + 1], cy);
            float dz = __fsub_rn(sx[3 * i + 2], cz);
            float d2 = __fmaf_rn(dz, dz, __fmaf_rn(dy, dy, __fmul_rn(dx, dx)));
            unsigned m = __ballot_sync(0xffffffffu, d2 < r2);
            while (m) {
                int src_l = __ffs(m) - 1;
                m &= m - 1;
                float cd2 = __shfl_sync(0xffffffffu, d2, src_l);
                unsigned mx = __reduce_max_sync(0xffffffffu, __float_as_uint(sd2));
                if (__float_as_uint(cd2) < mx) {
                    unsigned who =
                        __ballot_sync(0xffffffffu, __float_as_uint(sd2) == mx);
                    if (lane == __ffs(who) - 1) {
                        sd2 = cd2;
                        sidx = base + i0 + src_l;
                    }
                }
            }
        }
    }
    nbr[cid * KK + lane] = (sd2 < r2) ? sidx : (NN - 1);
}

// ---------------------------------------------------------------------------
// Fused MLP: gather -> (comb @ w1 + b1) -> gelu(tanh) -> LN -> @ w2 + b2 -> LN
// -> max over K. One block per center, 256 threads (8 warps x 32 lanes).
// Warp w owns rows 4w..4w+3. Weights read through L1 (w1+w2 = 209KB < 228KB).
// ---------------------------------------------------------------------------
__global__ void __launch_bounds__(256)
mlp_kernel(const float* __restrict__ x, const float* __restrict__ feat,
           const float* __restrict__ centers, const int* __restrict__ nbr,
           const float* __restrict__ w1, const float* __restrict__ b1,
           const float* __restrict__ g1, const float* __restrict__ be1,
           const float* __restrict__ w2, const float* __restrict__ b2,
           const float* __restrict__ g2, const float* __restrict__ be2,
           float* __restrict__ out) {
    __shared__ float s_comb[32][68];
    __shared__ float s_h1[32][272];
    __shared__ float s_wmax[8][128];
    __shared__ int s_nbr[32];
    __shared__ float s_ctr[3];

    int cid = blockIdx.x;
    int b = cid >> 11;
    int tid = threadIdx.x, w = tid >> 5, l = tid & 31;

    if (tid < 32) s_nbr[tid] = nbr[cid * KK + tid];
    if (tid < 3) s_ctr[tid] = centers[(size_t)cid * 3 + tid];
    __syncthreads();

    // gather comb = [features(64), rel(3)]
#pragma unroll
    for (int r = 0; r < 4; r++) {
        int k = w * 4 + r;
        int idx = s_nbr[k];
        const float2* frow = (const float2*)(feat + ((size_t)b * NN + idx) * CC);
        float2 v = frow[l];
        s_comb[k][2 * l] = v.x;
        s_comb[k][2 * l + 1] = v.y;
        if (l == 0) {
            const float* p = x + ((size_t)b * NN + idx) * 3;
            s_comb[k][64] = p[0] - s_ctr[0];
            s_comb[k][65] = p[1] - s_ctr[1];
            s_comb[k][66] = p[2] - s_ctr[2];
        }
    }
    __syncthreads();

    // ---- layer 1: rows 4w..4w+3; lane cols: 4l..4l+3, 128+4l..+3, 256+l(<268)
    const int jA = 4 * l, jB = 128 + 4 * l, jC = 256 + l;
    const bool hasC = (l < 12);
    const int k0 = 4 * w;
    float acc[4][9];
#pragma unroll
    for (int r = 0; r < 4; r++)
#pragma unroll
        for (int c = 0; c < 9; c++) acc[r][c] = 0.f;

    for (int i = 0; i < CIN; i++) {
        float cv[4];
#pragma unroll
        for (int r = 0; r < 4; r++) cv[r] = s_comb[k0 + r][i];
        const float* wr = w1 + i * HID;
        float4 wa = *(const float4*)(wr + jA);
        float4 wb = *(const float4*)(wr + jB);
        float wc = hasC ? wr[jC] : 0.f;
#pragma unroll
        for (int r = 0; r < 4; r++) {
            acc[r][0] += cv[r] * wa.x;
            acc[r][1] += cv[r] * wa.y;
            acc[r][2] += cv[r] * wa.z;
            acc[r][3] += cv[r] * wa.w;
            acc[r][4] += cv[r] * wb.x;
            acc[r][5] += cv[r] * wb.y;
            acc[r][6] += cv[r] * wb.z;
            acc[r][7] += cv[r] * wb.w;
            acc[r][8] += cv[r] * wc;
        }
    }

    // bias + gelu (tanh approximation — JAX default)
    {
        float4 bA = *(const float4*)(b1 + jA);
        float4 bB = *(const float4*)(b1 + jB);
        float bC = hasC ? b1[jC] : 0.f;
        float bias[9] = {bA.x, bA.y, bA.z, bA.w, bB.x, bB.y, bB.z, bB.w, bC};
#pragma unroll
        for (int r = 0; r < 4; r++)
#pragma unroll
            for (int c = 0; c < 9; c++) {
                float h = acc[r][c] + bias[c];
                float tr = 0.7978845608028654f * (h + 0.044715f * h * h * h);
                acc[r][c] = 0.5f * h * (1.0f + tanhf(tr));
            }
    }

    // LN over 268 (warp-wide)
    float sum[4], sq[4];
#pragma unroll
    for (int r = 0; r < 4; r++) {
        float s = 0.f, q = 0.f;
#pragma unroll
        for (int c = 0; c < 8; c++) {
            s += acc[r][c];
            q += acc[r][c] * acc[r][c];
        }
        if (hasC) {
            s += acc[r][8];
            q += acc[r][8] * acc[r][8];
        }
        sum[r] = s;
        sq[r] = q;
    }
#pragma unroll
    for (int o = 16; o; o >>= 1) {
#pragma unroll
        for (int r = 0; r < 4; r++) {
            sum[r] += __shfl_xor_sync(0xffffffffu, sum[r], o);
            sq[r] += __shfl_xor_sync(0xffffffffu, sq[r], o);
        }
    }
    {
        float4 gA = *(const float4*)(g1 + jA);
        float4 gB = *(const float4*)(g1 + jB);
        float gC = hasC ? g1[jC] : 0.f;
        float4 eA = *(const float4*)(be1 + jA);
        float4 eB = *(const float4*)(be1 + jB);
        float eC = hasC ? be1[jC] : 0.f;
        float gam[9] = {gA.x, gA.y, gA.z, gA.w, gB.x, gB.y, gB.z, gB.w, gC};
        float bet[9] = {eA.x, eA.y, eA.z, eA.w, eB.x, eB.y, eB.z, eB.w, eC};
#pragma unroll
        for (int r = 0; r < 4; r++) {
            float mu = sum[r] * (1.0f / 268.0f);
            float var = sq[r] * (1.0f / 268.0f) - mu * mu;
            float inv = rsqrtf(var + 1e-6f);
            int k = k0 + r;
            float o9[9];
#pragma unroll
            for (int c = 0; c < 9; c++)
                o9[c] = (acc[r][c] - mu) * inv * gam[c] + bet[c];
            *(float4*)&s_h1[k][jA] = make_float4(o9[0], o9[1], o9[2], o9[3]);
            *(float4*)&s_h1[k][jB] = make_float4(o9[4], o9[5], o9[6], o9[7]);
            if (hasC) s_h1[k][jC] = o9[8];
        }
    }
    __syncthreads();

    // ---- layer 2: rows 4w..4w+3, lane cols 4l..4l+3
    float a2[4][4];
#pragma unroll
    for (int r = 0; r < 4; r++)
#pragma unroll
        for (int c = 0; c < 4; c++) a2[r][c] = 0.f;
    const int o0 = 4 * l;
    for (int j = 0; j < HID; j++) {
        float h0 = s_h1[k0][j], h1v = s_h1[k0 + 1][j];
        float h2v = s_h1[k0 + 2][j], h3v = s_h1[k0 + 3][j];
        float4 wv = *(const float4*)(w2 + j * OUTD + o0);
        a2[0][0] += h0 * wv.x;  a2[0][1] += h0 * wv.y;
        a2[0][2] += h0 * wv.z;  a2[0][3] += h0 * wv.w;
        a2[1][0] += h1v * wv.x; a2[1][1] += h1v * wv.y;
        a2[1][2] += h1v * wv.z; a2[1][3] += h1v * wv.w;
        a2[2][0] += h2v * wv.x; a2[2][1] += h2v * wv.y;
        a2[2][2] += h2v * wv.z; a2[2][3] += h2v * wv.w;
        a2[3][0] += h3v * wv.x; a2[3][1] += h3v * wv.y;
        a2[3][2] += h3v * wv.z; a2[3][3] += h3v * wv.w;
    }
    {
        float4 bv = *(const float4*)(b2 + o0);
        float bias[4] = {bv.x, bv.y, bv.z, bv.w};
#pragma unroll
        for (int r = 0; r < 4; r++)
#pragma unroll
            for (int c = 0; c < 4; c++) a2[r][c] += bias[c];
    }
    // LN over 128 (warp-wide)
    float s2[4], q2[4];
#pragma unroll
    for (int r = 0; r < 4; r++) {
        float s = 0.f, q = 0.f;
#pragma unroll
        for (int c = 0; c < 4; c++) {
            s += a2[r][c];
            q += a2[r][c] * a2[r][c];
        }
        s2[r] = s;
        q2[r] = q;
    }
#pragma unroll
    for (int o = 16; o; o >>= 1) {
#pragma unroll
        for (int r = 0; r < 4; r++) {
            s2[r] += __shfl_xor_sync(0xffffffffu, s2[r], o);
            q2[r] += __shfl_xor_sync(0xffffffffu, q2[r], o);
        }
    }
    {
        float4 gv = *(const float4*)(g2 + o0);
        float4 ev = *(const float4*)(be2 + o0);
        float gam[4] = {gv.x, gv.y, gv.z, gv.w};
        float bet[4] = {ev.x, ev.y, ev.z, ev.w};
        float cmax[4];
#pragma unroll
        for (int c = 0; c < 4; c++) cmax[c] = -3.4e38f;
#pragma unroll
        for (int r = 0; r < 4; r++) {
            float mu = s2[r] * (1.0f / 128.0f);
            float var = q2[r] * (1.0f / 128.0f) - mu * mu;
            float inv = rsqrtf(var + 1e-6f);
#pragma unroll
            for (int c = 0; c < 4; c++) {
                float v = (a2[r][c] - mu) * inv * gam[c] + bet[c];
                cmax[c] = fmaxf(cmax[c], v);
            }
        }
#pragma unroll
        for (int c = 0; c < 4; c++) s_wmax[w][o0 + c] = cmax[c];
    }
    __syncthreads();
    if (tid < 128) {
        float m = s_wmax[0][tid];
#pragma unroll
        for (int ww = 1; ww < 8; ww++) m = fmaxf(m, s_wmax[ww][tid]);
        out[(size_t)cid * OUTD + tid] = m;
    }
}

// ---------------------------------------------------------------------------
extern "C" void kernel_launch(void* const* d_in, const int* in_sizes, int n_in,
                              void* d_out, int out_size) {
    const float* x = (const float*)d_in[0];
    const float* feat = (const float*)d_in[1];
    const int* first_idx = (const int*)d_in[2];
    const float* w1 = (const float*)d_in[3];
    const float* b1 = (const float*)d_in[4];
    const float* g1 = (const float*)d_in[5];
    const float* be1 = (const float*)d_in[6];
    const float* w2 = (const float*)d_in[7];
    const float* b2 = (const float*)d_in[8];
    const float* g2 = (const float*)d_in[9];
    const float* be2 = (const float*)d_in[10];

    float* centers = (float*)d_out;                    // [B, M, 3]
    float* out = (float*)d_out + (size_t)BB * MM * 3;  // [B, M, 128]

    int* nbr;
    cudaGetSymbolAddress((void**)&nbr, g_nbr);

    fps_kernel<<<BB, 1024>>>(x, first_idx, centers);
    bq_kernel<<<BB * MM / 4, 128>>>(x, centers, nbr);
    mlp_kernel<<<BB * MM, 256>>>(x, feat, centers, nbr, w1, b1, g1, be1, w2, b2,
                                 g2, be2, out);
}

// round 8
// speedup vs baseline: 1.4900x; 1.4900x over previous
#include <cuda_runtime.h>
#include <cstdint>
#include <cstddef>

#define BB 8
#define NN 8192
#define DD 3
#define CC 64
#define MM 2048
#define KK 32
#define CIN 67
#define HID 268
#define OUTD 128

__device__ int g_nbr[BB * MM * KK];

// ---------------- packed f32x2 helpers (per-lane IEEE rn == scalar) ----------
typedef unsigned long long u64;
static __device__ __forceinline__ u64 pk2(float lo, float hi) {
    u64 r;
    asm("mov.b64 %0, {%1, %2};" : "=l"(r) : "f"(lo), "f"(hi));
    return r;
}
static __device__ __forceinline__ void upk2(u64 v, float& lo, float& hi) {
    asm("mov.b64 {%0, %1}, %2;" : "=f"(lo), "=f"(hi) : "l"(v));
}
static __device__ __forceinline__ u64 f2add(u64 a, u64 b) {
    u64 r;
    asm("add.rn.f32x2 %0, %1, %2;" : "=l"(r) : "l"(a), "l"(b));
    return r;
}
static __device__ __forceinline__ u64 f2mul(u64 a, u64 b) {
    u64 r;
    asm("mul.rn.f32x2 %0, %1, %2;" : "=l"(r) : "l"(a), "l"(b));
    return r;
}
static __device__ __forceinline__ u64 f2fma(u64 a, u64 b, u64 c) {
    u64 r;
    asm("fma.rn.f32x2 %0, %1, %2, %3;" : "=l"(r) : "l"(a), "l"(b), "l"(c));
    return r;
}

// ---------------------------------------------------------------------------
// FPS v2: one block/batch, 512 threads, 16 pts/thread in packed f32x2 regs.
// Coords mirrored in dynamic smem (96KB) so the far point is read directly.
// Distance bits identical to R5: a-b == a+(-b), mul, fma, fma (rn each).
// Selection: global max d, then min index among maxima (atomicMin) — exact
// (value, lowest-index) semantics of jnp.argmax.
// ---------------------------------------------------------------------------
__global__ void __launch_bounds__(512) fps_kernel(
    const float* __restrict__ x, const int* __restrict__ first_idx,
    float* __restrict__ centers) {
    constexpr int T = 512;
    constexpr int PPT = NN / T;  // 16
    constexpr int NW = T / 32;   // 16 warps
    extern __shared__ float sh[];
    float* sxc = sh;
    float* syc = sh + NN;
    float* szc = sh + 2 * NN;
    __shared__ unsigned s_red[2][32];
    __shared__ int s_far[2];

    int b = blockIdx.x, t = threadIdx.x;
    int lane = t & 31, warp = t >> 5;
    const float* xb = x + (size_t)b * NN * 3;

    u64 px2[PPT / 2], py2[PPT / 2], pz2[PPT / 2];
    float d[PPT];
#pragma unroll
    for (int j = 0; j < PPT / 2; j++) {
        int n0 = t + T * (2 * j), n1 = t + T * (2 * j + 1);
        float ax = xb[n0 * 3 + 0], ay = xb[n0 * 3 + 1], az = xb[n0 * 3 + 2];
        float bx = xb[n1 * 3 + 0], by = xb[n1 * 3 + 1], bz = xb[n1 * 3 + 2];
        sxc[n0] = ax; syc[n0] = ay; szc[n0] = az;
        sxc[n1] = bx; syc[n1] = by; szc[n1] = bz;
        px2[j] = pk2(ax, bx); py2[j] = pk2(ay, by); pz2[j] = pk2(az, bz);
    }
    if (t == 0) { s_far[0] = 0x7fffffff; s_far[1] = 0x7fffffff; }
    if (t >= NW && t < 32) { s_red[0][t] = 0u; s_red[1][t] = 0u; }
    int fi = first_idx[b];
    __syncthreads();

    float fx = sxc[fi], fy = syc[fi], fz = szc[fi];
    if (t == 0) {
        float* c = centers + (size_t)b * MM * 3;
        c[0] = fx; c[1] = fy; c[2] = fz;
    }
    {
        u64 nfx = pk2(-fx, -fx), nfy = pk2(-fy, -fy), nfz = pk2(-fz, -fz);
#pragma unroll
        for (int j = 0; j < PPT / 2; j++) {
            u64 dxp = f2add(px2[j], nfx);
            u64 dyp = f2add(py2[j], nfy);
            u64 dzp = f2add(pz2[j], nfz);
            u64 dd = f2fma(dzp, dzp, f2fma(dyp, dyp, f2mul(dxp, dxp)));
            upk2(dd, d[2 * j], d[2 * j + 1]);
        }
    }

    for (int it = 1; it < MM; it++) {
        int par = it & 1;
        float tmax = d[0];
#pragma unroll
        for (int s = 1; s < PPT; s++) tmax = fmaxf(tmax, d[s]);
        unsigned tb = __float_as_uint(tmax);  // all d >= 0: uint order == float
        unsigned wm = __reduce_max_sync(0xffffffffu, tb);
        if (lane == 0) s_red[par][warp] = wm;
        __syncthreads();
        unsigned gb = __reduce_max_sync(0xffffffffu, s_red[par][lane]);
        if (tb == gb) {
            int bim = 0x7fffffff;
#pragma unroll
            for (int s = PPT - 1; s >= 0; s--)
                if (__float_as_uint(d[s]) == gb) bim = t + T * s;
            atomicMin(&s_far[par], bim);
        }
        if (t == 0) s_far[par ^ 1] = 0x7fffffff;
        __syncthreads();
        int far = s_far[par];
        fx = sxc[far]; fy = syc[far]; fz = szc[far];
        if (t == 0) {
            float* c = centers + ((size_t)b * MM + it) * 3;
            c[0] = fx; c[1] = fy; c[2] = fz;
        }
        u64 nfx = pk2(-fx, -fx), nfy = pk2(-fy, -fy), nfz = pk2(-fz, -fz);
#pragma unroll
        for (int j = 0; j < PPT / 2; j++) {
            u64 dxp = f2add(px2[j], nfx);
            u64 dyp = f2add(py2[j], nfy);
            u64 dzp = f2add(pz2[j], nfz);
            u64 dd = f2fma(dzp, dzp, f2fma(dyp, dyp, f2mul(dxp, dxp)));
            float n0, n1;
            upk2(dd, n0, n1);
            d[2 * j] = fminf(d[2 * j], n0);
            d[2 * j + 1] = fminf(d[2 * j + 1], n1);
        }
    }
}

// ---------------------------------------------------------------------------
// Ball query: unchanged from the passing R5 kernel (distance bits identical).
// ---------------------------------------------------------------------------
__global__ void bq_kernel(const float* __restrict__ x,
                          const float* __restrict__ centers,
                          int* __restrict__ nbr) {
    constexpr int WPB = 4;
    constexpr int TILE = 2048;
    __shared__ float sx[TILE * 3];

    int w = threadIdx.x >> 5;
    int lane = threadIdx.x & 31;
    int cid = blockIdx.x * WPB + w;
    int b = cid >> 11;
    const float* xb = x + (size_t)b * NN * 3;

    float cx, cy, cz;
    {
        const float* c = centers + (size_t)cid * 3;
        cx = c[0]; cy = c[1]; cz = c[2];
    }
    const float r2 = 0.09f;
    float sd2 = __int_as_float(0x7f800000);
    int sidx = NN - 1;

    for (int tile = 0; tile < NN / TILE; tile++) {
        __syncthreads();
        const float4* src = (const float4*)(xb + tile * TILE * 3);
        for (int i = threadIdx.x; i < TILE * 3 / 4; i += WPB * 32)
            ((float4*)sx)[i] = src[i];
        __syncthreads();
        int base = tile * TILE;
        for (int i0 = 0; i0 < TILE; i0 += 32) {
            int i = i0 + lane;
            float dx = __fsub_rn(sx[3 * i + 0], cx);
            float dy = __fsub_rn(sx[3 * i + 1], cy);
            float dz = __fsub_rn(sx[3 * i + 2], cz);
            float d2 = __fmaf_rn(dz, dz, __fmaf_rn(dy, dy, __fmul_rn(dx, dx)));
            unsigned m = __ballot_sync(0xffffffffu, d2 < r2);
            while (m) {
                int src_l = __ffs(m) - 1;
                m &= m - 1;
                float cd2 = __shfl_sync(0xffffffffu, d2, src_l);
                unsigned mx = __reduce_max_sync(0xffffffffu, __float_as_uint(sd2));
                if (__float_as_uint(cd2) < mx) {
                    unsigned who =
                        __ballot_sync(0xffffffffu, __float_as_uint(sd2) == mx);
                    if (lane == __ffs(who) - 1) {
                        sd2 = cd2;
                        sidx = base + i0 + src_l;
                    }
                }
            }
        }
    }
    nbr[cid * KK + lane] = (sd2 < r2) ? sidx : (NN - 1);
}

// fast tanh-gelu: exp2-based tanh (MUFU). Continuous op, ~1e-6 effect.
static __device__ __forceinline__ float fast_gelu(float h) {
    float u = 0.7978845608028654f * __fmaf_rn(0.044715f * h, h * h, h);
    u = fminf(fmaxf(u, -9.0f), 9.0f);
    float e = __expf(2.0f * u);
    float t = (e - 1.0f) * __frcp_rn(e + 1.0f);
    return 0.5f * h * (1.0f + t);
}

// ---------------------------------------------------------------------------
// Fused MLP v2: one block/center, 128 threads (4 warps), 8 rows/warp.
// Packed f32x2 FMA halves FFMA issue; accumulation order over i/j preserved
// exactly (per-lane rn) -> layer outputs bitwise identical to R5.
// ---------------------------------------------------------------------------
__global__ void __launch_bounds__(128)
mlp_kernel(const float* __restrict__ x, const float* __restrict__ feat,
           const float* __restrict__ centers, const int* __restrict__ nbr,
           const float* __restrict__ w1, const float* __restrict__ b1,
           const float* __restrict__ g1, const float* __restrict__ be1,
           const float* __restrict__ w2, const float* __restrict__ b2,
           const float* __restrict__ g2, const float* __restrict__ be2,
           float* __restrict__ out) {
    __shared__ __align__(16) float s_comb[32][68];
    __shared__ __align__(16) float s_h1[32][272];
    __shared__ float s_wmax[4][128];
    __shared__ int s_nbr[32];
    __shared__ float s_ctr[3];

    int cid = blockIdx.x;
    int b = cid >> 11;
    int tid = threadIdx.x, w = tid >> 5, l = tid & 31;
    const int k0 = 8 * w;

    if (tid < 32) s_nbr[tid] = nbr[cid * KK + tid];
    if (tid < 3) s_ctr[tid] = centers[(size_t)cid * 3 + tid];
    __syncthreads();

    // gather comb = [features(64), rel(3)]
#pragma unroll
    for (int r = 0; r < 8; r++) {
        int k = k0 + r;
        int idx = s_nbr[k];
        const float2* frow = (const float2*)(feat + ((size_t)b * NN + idx) * CC);
        float2 v = frow[l];
        s_comb[k][2 * l] = v.x;
        s_comb[k][2 * l + 1] = v.y;
        if (l == 0) {
            const float* p = x + ((size_t)b * NN + idx) * 3;
            s_comb[k][64] = p[0] - s_ctr[0];
            s_comb[k][65] = p[1] - s_ctr[1];
            s_comb[k][66] = p[2] - s_ctr[2];
        }
    }
    __syncthreads();

    // ---- layer 1: lane cols 4l..4l+3, 128+4l..+3, 256+l (l<12); 8 rows/warp
    const int jA = 4 * l, jB = 128 + 4 * l, jC = 256 + l;
    const bool hasC = (l < 12);

    u64 accP[8][4];
    float acc9[8];
#pragma unroll
    for (int r = 0; r < 8; r++) {
        acc9[r] = 0.f;
#pragma unroll
        for (int q = 0; q < 4; q++) accP[r][q] = 0ull;
    }

    for (int i4 = 0; i4 < 16; i4++) {  // i = 0..63
        float4 cv4[8];
#pragma unroll
        for (int r = 0; r < 8; r++)
            cv4[r] = *(const float4*)&s_comb[k0 + r][i4 * 4];
#pragma unroll
        for (int ii = 0; ii < 4; ii++) {
            const float* wr = w1 + (i4 * 4 + ii) * HID;
            float4 wa = *(const float4*)(wr + jA);
            float4 wb = *(const float4*)(wr + jB);
            float wc = hasC ? wr[jC] : 0.f;
            u64 pw0 = pk2(wa.x, wa.y), pw1 = pk2(wa.z, wa.w);
            u64 pw2 = pk2(wb.x, wb.y), pw3 = pk2(wb.z, wb.w);
#pragma unroll
            for (int r = 0; r < 8; r++) {
                float c = (ii == 0) ? cv4[r].x
                        : (ii == 1) ? cv4[r].y
                        : (ii == 2) ? cv4[r].z : cv4[r].w;
                u64 cp = pk2(c, c);
                accP[r][0] = f2fma(cp, pw0, accP[r][0]);
                accP[r][1] = f2fma(cp, pw1, accP[r][1]);
                accP[r][2] = f2fma(cp, pw2, accP[r][2]);
                accP[r][3] = f2fma(cp, pw3, accP[r][3]);
                acc9[r] = __fmaf_rn(c, wc, acc9[r]);
            }
        }
    }
    for (int i = 64; i < CIN; i++) {  // tail
        const float* wr = w1 + i * HID;
        float4 wa = *(const float4*)(wr + jA);
        float4 wb = *(const float4*)(wr + jB);
        float wc = hasC ? wr[jC] : 0.f;
        u64 pw0 = pk2(wa.x, wa.y), pw1 = pk2(wa.z, wa.w);
        u64 pw2 = pk2(wb.x, wb.y), pw3 = pk2(wb.z, wb.w);
#pragma unroll
        for (int r = 0; r < 8; r++) {
            float c = s_comb[k0 + r][i];
            u64 cp = pk2(c, c);
            accP[r][0] = f2fma(cp, pw0, accP[r][0]);
            accP[r][1] = f2fma(cp, pw1, accP[r][1]);
            accP[r][2] = f2fma(cp, pw2, accP[r][2]);
            accP[r][3] = f2fma(cp, pw3, accP[r][3]);
            acc9[r] = __fmaf_rn(c, wc, acc9[r]);
        }
    }

    float acc[8][9];
#pragma unroll
    for (int r = 0; r < 8; r++) {
        upk2(accP[r][0], acc[r][0], acc[r][1]);
        upk2(accP[r][1], acc[r][2], acc[r][3]);
        upk2(accP[r][2], acc[r][4], acc[r][5]);
        upk2(accP[r][3], acc[r][6], acc[r][7]);
        acc[r][8] = acc9[r];
    }

    // bias + gelu
    {
        float4 bA = *(const float4*)(b1 + jA);
        float4 bB = *(const float4*)(b1 + jB);
        float bC = hasC ? b1[jC] : 0.f;
        float bias[9] = {bA.x, bA.y, bA.z, bA.w, bB.x, bB.y, bB.z, bB.w, bC};
#pragma unroll
        for (int r = 0; r < 8; r++)
#pragma unroll
            for (int c = 0; c < 9; c++)
                acc[r][c] = fast_gelu(acc[r][c] + bias[c]);
    }

    // LN over 268 (warp-wide)
    float sum[8], sq[8];
#pragma unroll
    for (int r = 0; r < 8; r++) {
        float s = 0.f, q = 0.f;
#pragma unroll
        for (int c = 0; c < 8; c++) {
            s += acc[r][c];
            q += acc[r][c] * acc[r][c];
        }
        if (hasC) {
            s += acc[r][8];
            q += acc[r][8] * acc[r][8];
        }
        sum[r] = s;
        sq[r] = q;
    }
#pragma unroll
    for (int o = 16; o; o >>= 1) {
#pragma unroll
        for (int r = 0; r < 8; r++) {
            sum[r] += __shfl_xor_sync(0xffffffffu, sum[r], o);
            sq[r] += __shfl_xor_sync(0xffffffffu, sq[r], o);
        }
    }
    {
        float4 gA = *(const float4*)(g1 + jA);
        float4 gB = *(const float4*)(g1 + jB);
        float gC = hasC ? g1[jC] : 0.f;
        float4 eA = *(const float4*)(be1 + jA);
        float4 eB = *(const float4*)(be1 + jB);
        float eC = hasC ? be1[jC] : 0.f;
        float gam[9] = {gA.x, gA.y, gA.z, gA.w, gB.x, gB.y, gB.z, gB.w, gC};
        float bet[9] = {eA.x, eA.y, eA.z, eA.w, eB.x, eB.y, eB.z, eB.w, eC};
#pragma unroll
        for (int r = 0; r < 8; r++) {
            float mu = sum[r] * (1.0f / 268.0f);
            float var = sq[r] * (1.0f / 268.0f) - mu * mu;
            float inv = rsqrtf(var + 1e-6f);
            int k = k0 + r;
            float o9[9];
#pragma unroll
            for (int c = 0; c < 9; c++)
                o9[c] = (acc[r][c] - mu) * inv * gam[c] + bet[c];
            *(float4*)&s_h1[k][jA] = make_float4(o9[0], o9[1], o9[2], o9[3]);
            *(float4*)&s_h1[k][jB] = make_float4(o9[4], o9[5], o9[6], o9[7]);
            if (hasC) s_h1[k][jC] = o9[8];
        }
    }
    __syncthreads();

    // ---- layer 2: 8 rows/warp, lane cols 4l..4l+3 (packed pairs)
    const int o0 = 4 * l;
    u64 a2p[8][2];
#pragma unroll
    for (int r = 0; r < 8; r++) { a2p[r][0] = 0ull; a2p[r][1] = 0ull; }

    for (int j4 = 0; j4 < HID / 4; j4++) {  // 67 chunks, exact
        float4 h4[8];
#pragma unroll
        for (int r = 0; r < 8; r++)
            h4[r] = *(const float4*)&s_h1[k0 + r][j4 * 4];
#pragma unroll
        for (int jj = 0; jj < 4; jj++) {
            int j = j4 * 4 + jj;
            float4 wv = *(const float4*)(w2 + j * OUTD + o0);
            u64 pw0 = pk2(wv.x, wv.y), pw1 = pk2(wv.z, wv.w);
#pragma unroll
            for (int r = 0; r < 8; r++) {
                float hv = (jj == 0) ? h4[r].x
                         : (jj == 1) ? h4[r].y
                         : (jj == 2) ? h4[r].z : h4[r].w;
                u64 hp = pk2(hv, hv);
                a2p[r][0] = f2fma(hp, pw0, a2p[r][0]);
                a2p[r][1] = f2fma(hp, pw1, a2p[r][1]);
            }
        }
    }

    float a2[8][4];
#pragma unroll
    for (int r = 0; r < 8; r++) {
        upk2(a2p[r][0], a2[r][0], a2[r][1]);
        upk2(a2p[r][1], a2[r][2], a2[r][3]);
    }
    {
        float4 bv = *(const float4*)(b2 + o0);
        float bias[4] = {bv.x, bv.y, bv.z, bv.w};
#pragma unroll
        for (int r = 0; r < 8; r++)
#pragma unroll
            for (int c = 0; c < 4; c++) a2[r][c] += bias[c];
    }
    // LN over 128 (warp-wide)
    float s2[8], q2[8];
#pragma unroll
    for (int r = 0; r < 8; r++) {
        float s = 0.f, q = 0.f;
#pragma unroll
        for (int c = 0; c < 4; c++) {
            s += a2[r][c];
            q += a2[r][c] * a2[r][c];
        }
        s2[r] = s;
        q2[r] = q;
    }
#pragma unroll
    for (int o = 16; o; o >>= 1) {
#pragma unroll
        for (int r = 0; r < 8; r++) {
            s2[r] += __shfl_xor_sync(0xffffffffu, s2[r], o);
            q2[r] += __shfl_xor_sync(0xffffffffu, q2[r], o);
        }
    }
    {
        float4 gv = *(const float4*)(g2 + o0);
        float4 ev = *(const float4*)(be2 + o0);
        float gam[4] = {gv.x, gv.y, gv.z, gv.w};
        float bet[4] = {ev.x, ev.y, ev.z, ev.w};
        float cmax[4];
#pragma unroll
        for (int c = 0; c < 4; c++) cmax[c] = -3.4e38f;
#pragma unroll
        for (int r = 0; r < 8; r++) {
            float mu = s2[r] * (1.0f / 128.0f);
            float var = q2[r] * (1.0f / 128.0f) - mu * mu;
            float inv = rsqrtf(var + 1e-6f);
#pragma unroll
            for (int c = 0; c < 4; c++) {
                float v = (a2[r][c] - mu) * inv * gam[c] + bet[c];
                cmax[c] = fmaxf(cmax[c], v);
            }
        }
#pragma unroll
        for (int c = 0; c < 4; c++) s_wmax[w][o0 + c] = cmax[c];
    }
    __syncthreads();
    if (tid < 128) {
        float m = s_wmax[0][tid];
#pragma unroll
        for (int ww = 1; ww < 4; ww++) m = fmaxf(m, s_wmax[ww][tid]);
        out[(size_t)cid * OUTD + tid] = m;
    }
}

// ---------------------------------------------------------------------------
extern "C" void kernel_launch(void* const* d_in, const int* in_sizes, int n_in,
                              void* d_out, int out_size) {
    const float* x = (const float*)d_in[0];
    const float* feat = (const float*)d_in[1];
    const int* first_idx = (const int*)d_in[2];
    const float* w1 = (const float*)d_in[3];
    const float* b1 = (const float*)d_in[4];
    const float* g1 = (const float*)d_in[5];
    const float* be1 = (const float*)d_in[6];
    const float* w2 = (const float*)d_in[7];
    const float* b2 = (const float*)d_in[8];
    const float* g2 = (const float*)d_in[9];
    const float* be2 = (const float*)d_in[10];

    float* centers = (float*)d_out;                    // [B, M, 3]
    float* out = (float*)d_out + (size_t)BB * MM * 3;  // [B, M, 128]

    int* nbr;
    cudaGetSymbolAddress((void**)&nbr, g_nbr);

    const int fps_smem = 3 * NN * (int)sizeof(float);  // 96KB coords mirror
    cudaFuncSetAttribute(fps_kernel, cudaFuncAttributeMaxDynamicSharedMemorySize,
                         fps_smem);

    fps_kernel<<<BB, 512, fps_smem>>>(x, first_idx, centers);
    bq_kernel<<<BB * MM / 4, 128>>>(x, centers, nbr);
    mlp_kernel<<<BB * MM, 128>>>(x, feat, centers, nbr, w1, b1, g1, be1, w2, b2,
                                 g2, be2, out);
}

// round 9
// speedup vs baseline: 1.5158x; 1.0173x over previous
#include <cuda_runtime.h>
#include <cstdint>
#include <cstddef>

#define BB 8
#define NN 8192
#define DD 3
#define CC 64
#define MM 2048
#define KK 32
#define CIN 67
#define HID 268
#define OUTD 128

__device__ int g_nbr[BB * MM * KK];

// ---------------- packed f32x2 helpers (per-lane IEEE rn == scalar) ----------
typedef unsigned long long u64;
static __device__ __forceinline__ u64 pk2(float lo, float hi) {
    u64 r;
    asm("mov.b64 %0, {%1, %2};" : "=l"(r) : "f"(lo), "f"(hi));
    return r;
}
static __device__ __forceinline__ void upk2(u64 v, float& lo, float& hi) {
    asm("mov.b64 {%0, %1}, %2;" : "=f"(lo), "=f"(hi) : "l"(v));
}
static __device__ __forceinline__ u64 f2add(u64 a, u64 b) {
    u64 r;
    asm("add.rn.f32x2 %0, %1, %2;" : "=l"(r) : "l"(a), "l"(b));
    return r;
}
static __device__ __forceinline__ u64 f2mul(u64 a, u64 b) {
    u64 r;
    asm("mul.rn.f32x2 %0, %1, %2;" : "=l"(r) : "l"(a), "l"(b));
    return r;
}
static __device__ __forceinline__ u64 f2fma(u64 a, u64 b, u64 c) {
    u64 r;
    asm("fma.rn.f32x2 %0, %1, %2, %3;" : "=l"(r) : "l"(a), "l"(b), "l"(c));
    return r;
}

// ---------------------------------------------------------------------------
// FPS v3: one block/batch, 512 threads, 16 pts/thread packed. Per-iteration
// argmax scan fused into the distance-update loop (tmax carried across
// iterations; identical fmax value set -> identical selection bits).
// Distance bits identical to R5/R8: add(neg), mul, fma, fma (rn each).
// ---------------------------------------------------------------------------
__global__ void __launch_bounds__(512) fps_kernel(
    const float* __restrict__ x, const int* __restrict__ first_idx,
    float* __restrict__ centers) {
    constexpr int T = 512;
    constexpr int PPT = NN / T;  // 16
    constexpr int NW = T / 32;   // 16 warps
    extern __shared__ float sh[];
    float* sxc = sh;
    float* syc = sh + NN;
    float* szc = sh + 2 * NN;
    __shared__ unsigned s_red[2][32];
    __shared__ int s_far[2];

    int b = blockIdx.x, t = threadIdx.x;
    int lane = t & 31, warp = t >> 5;
    const float* xb = x + (size_t)b * NN * 3;

    u64 px2[PPT / 2], py2[PPT / 2], pz2[PPT / 2];
    float d[PPT];
#pragma unroll
    for (int j = 0; j < PPT / 2; j++) {
        int n0 = t + T * (2 * j), n1 = t + T * (2 * j + 1);
        float ax = xb[n0 * 3 + 0], ay = xb[n0 * 3 + 1], az = xb[n0 * 3 + 2];
        float bx = xb[n1 * 3 + 0], by = xb[n1 * 3 + 1], bz = xb[n1 * 3 + 2];
        sxc[n0] = ax; syc[n0] = ay; szc[n0] = az;
        sxc[n1] = bx; syc[n1] = by; szc[n1] = bz;
        px2[j] = pk2(ax, bx); py2[j] = pk2(ay, by); pz2[j] = pk2(az, bz);
    }
    if (t == 0) { s_far[0] = 0x7fffffff; s_far[1] = 0x7fffffff; }
    if (t >= NW && t < 32) { s_red[0][t] = 0u; s_red[1][t] = 0u; }
    int fi = first_idx[b];
    __syncthreads();

    float fx = sxc[fi], fy = syc[fi], fz = szc[fi];
    if (t == 0) {
        float* c = centers + (size_t)b * MM * 3;
        c[0] = fx; c[1] = fy; c[2] = fz;
    }
    float tmax = -1.0f;
    {
        u64 nfx = pk2(-fx, -fx), nfy = pk2(-fy, -fy), nfz = pk2(-fz, -fz);
#pragma unroll
        for (int j = 0; j < PPT / 2; j++) {
            u64 dxp = f2add(px2[j], nfx);
            u64 dyp = f2add(py2[j], nfy);
            u64 dzp = f2add(pz2[j], nfz);
            u64 dd = f2fma(dzp, dzp, f2fma(dyp, dyp, f2mul(dxp, dxp)));
            upk2(dd, d[2 * j], d[2 * j + 1]);
            tmax = fmaxf(tmax, d[2 * j]);
            tmax = fmaxf(tmax, d[2 * j + 1]);
        }
    }

    for (int it = 1; it < MM; it++) {
        int par = it & 1;
        unsigned tb = __float_as_uint(tmax);  // all d >= 0: uint order == float
        unsigned wm = __reduce_max_sync(0xffffffffu, tb);
        if (lane == 0) s_red[par][warp] = wm;
        __syncthreads();
        unsigned gb = __reduce_max_sync(0xffffffffu, s_red[par][lane]);
        if (tb == gb) {
            int bim = 0x7fffffff;
#pragma unroll
            for (int s = PPT - 1; s >= 0; s--)
                if (__float_as_uint(d[s]) == gb) bim = t + T * s;
            atomicMin(&s_far[par], bim);
        }
        if (t == 0) s_far[par ^ 1] = 0x7fffffff;
        __syncthreads();
        int far = s_far[par];
        fx = sxc[far]; fy = syc[far]; fz = szc[far];
        if (t == 0) {
            float* c = centers + ((size_t)b * MM + it) * 3;
            c[0] = fx; c[1] = fy; c[2] = fz;
        }
        u64 nfx = pk2(-fx, -fx), nfy = pk2(-fy, -fy), nfz = pk2(-fz, -fz);
        tmax = -1.0f;
#pragma unroll
        for (int j = 0; j < PPT / 2; j++) {
            u64 dxp = f2add(px2[j], nfx);
            u64 dyp = f2add(py2[j], nfy);
            u64 dzp = f2add(pz2[j], nfz);
            u64 dd = f2fma(dzp, dzp, f2fma(dyp, dyp, f2mul(dxp, dxp)));
            float n0, n1;
            upk2(dd, n0, n1);
            d[2 * j] = fminf(d[2 * j], n0);
            d[2 * j + 1] = fminf(d[2 * j + 1], n1);
            tmax = fmaxf(tmax, d[2 * j]);
            tmax = fmaxf(tmax, d[2 * j + 1]);
        }
    }
}

// ---------------------------------------------------------------------------
// Ball query: unchanged (distance/selection bits identical).
// ---------------------------------------------------------------------------
__global__ void bq_kernel(const float* __restrict__ x,
                          const float* __restrict__ centers,
                          int* __restrict__ nbr) {
    constexpr int WPB = 4;
    constexpr int TILE = 2048;
    __shared__ float sx[TILE * 3];

    int w = threadIdx.x >> 5;
    int lane = threadIdx.x & 31;
    int cid = blockIdx.x * WPB + w;
    int b = cid >> 11;
    const float* xb = x + (size_t)b * NN * 3;

    float cx, cy, cz;
    {
        const float* c = centers + (size_t)cid * 3;
        cx = c[0]; cy = c[1]; cz = c[2];
    }
    const float r2 = 0.09f;
    float sd2 = __int_as_float(0x7f800000);
    int sidx = NN - 1;

    for (int tile = 0; tile < NN / TILE; tile++) {
        __syncthreads();
        const float4* src = (const float4*)(xb + tile * TILE * 3);
        for (int i = threadIdx.x; i < TILE * 3 / 4; i += WPB * 32)
            ((float4*)sx)[i] = src[i];
        __syncthreads();
        int base = tile * TILE;
        for (int i0 = 0; i0 < TILE; i0 += 32) {
            int i = i0 + lane;
            float dx = __fsub_rn(sx[3 * i + 0], cx);
            float dy = __fsub_rn(sx[3 * i + 1], cy);
            float dz = __fsub_rn(sx[3 * i + 2], cz);
            float d2 = __fmaf_rn(dz, dz, __fmaf_rn(dy, dy, __fmul_rn(dx, dx)));
            unsigned m = __ballot_sync(0xffffffffu, d2 < r2);
            while (m) {
                int src_l = __ffs(m) - 1;
                m &= m - 1;
                float cd2 = __shfl_sync(0xffffffffu, d2, src_l);
                unsigned mx = __reduce_max_sync(0xffffffffu, __float_as_uint(sd2));
                if (__float_as_uint(cd2) < mx) {
                    unsigned who =
                        __ballot_sync(0xffffffffu, __float_as_uint(sd2) == mx);
                    if (lane == __ffs(who) - 1) {
                        sd2 = cd2;
                        sidx = base + i0 + src_l;
                    }
                }
            }
        }
    }
    nbr[cid * KK + lane] = (sd2 < r2) ? sidx : (NN - 1);
}

// fast tanh-gelu: exp2-based tanh (MUFU). Continuous op, ~1e-6 effect.
static __device__ __forceinline__ float fast_gelu(float h) {
    float u = 0.7978845608028654f * __fmaf_rn(0.044715f * h, h * h, h);
    u = fminf(fmaxf(u, -9.0f), 9.0f);
    float e = __expf(2.0f * u);
    float t = (e - 1.0f) * __frcp_rn(e + 1.0f);
    return 0.5f * h * (1.0f + t);
}

// ---------------------------------------------------------------------------
// Fused MLP v3: one block/center, 128 threads (4 warps), 8 rows/warp, packed
// f32x2 FMA. NEW: s_comb overlays s_h1 (comb dead after accumulation; extra
// barrier inserted) -> block smem 45.5KB -> 37.4KB -> up to 5 blocks/SM.
// All arithmetic bit-identical to R8.
// ---------------------------------------------------------------------------
__global__ void __launch_bounds__(128)
mlp_kernel(const float* __restrict__ x, const float* __restrict__ feat,
           const float* __restrict__ centers, const int* __restrict__ nbr,
           const float* __restrict__ w1, const float* __restrict__ b1,
           const float* __restrict__ g1, const float* __restrict__ be1,
           const float* __restrict__ w2, const float* __restrict__ b2,
           const float* __restrict__ g2, const float* __restrict__ be2,
           float* __restrict__ out) {
    __shared__ __align__(16) float s_h1[32][272];   // also hosts s_comb overlay
    __shared__ float s_wmax[4][128];
    __shared__ int s_nbr[32];
    __shared__ float s_ctr[3];

    float (*s_comb)[68] = (float(*)[68]) & s_h1[0][0];  // overlay, dead pre-LN

    int cid = blockIdx.x;
    int b = cid >> 11;
    int tid = threadIdx.x, w = tid >> 5, l = tid & 31;
    const int k0 = 8 * w;

    if (tid < 32) s_nbr[tid] = nbr[cid * KK + tid];
    if (tid < 3) s_ctr[tid] = centers[(size_t)cid * 3 + tid];
    __syncthreads();

    // gather comb = [features(64), rel(3)]
#pragma unroll
    for (int r = 0; r < 8; r++) {
        int k = k0 + r;
        int idx = s_nbr[k];
        const float2* frow = (const float2*)(feat + ((size_t)b * NN + idx) * CC);
        float2 v = frow[l];
        s_comb[k][2 * l] = v.x;
        s_comb[k][2 * l + 1] = v.y;
        if (l == 0) {
            const float* p = x + ((size_t)b * NN + idx) * 3;
            s_comb[k][64] = p[0] - s_ctr[0];
            s_comb[k][65] = p[1] - s_ctr[1];
            s_comb[k][66] = p[2] - s_ctr[2];
        }
    }
    __syncthreads();

    // ---- layer 1: lane cols 4l..4l+3, 128+4l..+3, 256+l (l<12); 8 rows/warp
    const int jA = 4 * l, jB = 128 + 4 * l, jC = 256 + l;
    const bool hasC = (l < 12);

    u64 accP[8][4];
    float acc9[8];
#pragma unroll
    for (int r = 0; r < 8; r++) {
        acc9[r] = 0.f;
#pragma unroll
        for (int q = 0; q < 4; q++) accP[r][q] = 0ull;
    }

    for (int i4 = 0; i4 < 16; i4++) {  // i = 0..63
        float4 cv4[8];
#pragma unroll
        for (int r = 0; r < 8; r++)
            cv4[r] = *(const float4*)&s_comb[k0 + r][i4 * 4];
#pragma unroll
        for (int ii = 0; ii < 4; ii++) {
            const float* wr = w1 + (i4 * 4 + ii) * HID;
            float4 wa = *(const float4*)(wr + jA);
            float4 wb = *(const float4*)(wr + jB);
            float wc = hasC ? wr[jC] : 0.f;
            u64 pw0 = pk2(wa.x, wa.y), pw1 = pk2(wa.z, wa.w);
            u64 pw2 = pk2(wb.x, wb.y), pw3 = pk2(wb.z, wb.w);
#pragma unroll
            for (int r = 0; r < 8; r++) {
                float c = (ii == 0) ? cv4[r].x
                        : (ii == 1) ? cv4[r].y
                        : (ii == 2) ? cv4[r].z : cv4[r].w;
                u64 cp = pk2(c, c);
                accP[r][0] = f2fma(cp, pw0, accP[r][0]);
                accP[r][1] = f2fma(cp, pw1, accP[r][1]);
                accP[r][2] = f2fma(cp, pw2, accP[r][2]);
                accP[r][3] = f2fma(cp, pw3, accP[r][3]);
                acc9[r] = __fmaf_rn(c, wc, acc9[r]);
            }
        }
    }
    for (int i = 64; i < CIN; i++) {  // tail
        const float* wr = w1 + i * HID;
        float4 wa = *(const float4*)(wr + jA);
        float4 wb = *(const float4*)(wr + jB);
        float wc = hasC ? wr[jC] : 0.f;
        u64 pw0 = pk2(wa.x, wa.y), pw1 = pk2(wa.z, wa.w);
        u64 pw2 = pk2(wb.x, wb.y), pw3 = pk2(wb.z, wb.w);
#pragma unroll
        for (int r = 0; r < 8; r++) {
            float c = s_comb[k0 + r][i];
            u64 cp = pk2(c, c);
            accP[r][0] = f2fma(cp, pw0, accP[r][0]);
            accP[r][1] = f2fma(cp, pw1, accP[r][1]);
            accP[r][2] = f2fma(cp, pw2, accP[r][2]);
            accP[r][3] = f2fma(cp, pw3, accP[r][3]);
            acc9[r] = __fmaf_rn(c, wc, acc9[r]);
        }
    }

    // all comb reads are done block-wide before s_h1 (overlay) is written
    __syncthreads();

    float acc[8][9];
#pragma unroll
    for (int r = 0; r < 8; r++) {
        upk2(accP[r][0], acc[r][0], acc[r][1]);
        upk2(accP[r][1], acc[r][2], acc[r][3]);
        upk2(accP[r][2], acc[r][4], acc[r][5]);
        upk2(accP[r][3], acc[r][6], acc[r][7]);
        acc[r][8] = acc9[r];
    }

    // bias + gelu
    {
        float4 bA = *(const float4*)(b1 + jA);
        float4 bB = *(const float4*)(b1 + jB);
        float bC = hasC ? b1[jC] : 0.f;
        float bias[9] = {bA.x, bA.y, bA.z, bA.w, bB.x, bB.y, bB.z, bB.w, bC};
#pragma unroll
        for (int r = 0; r < 8; r++)
#pragma unroll
            for (int c = 0; c < 9; c++)
                acc[r][c] = fast_gelu(acc[r][c] + bias[c]);
    }

    // LN over 268 (warp-wide)
    float sum[8], sq[8];
#pragma unroll
    for (int r = 0; r < 8; r++) {
        float s = 0.f, q = 0.f;
#pragma unroll
        for (int c = 0; c < 8; c++) {
            s += acc[r][c];
            q += acc[r][c] * acc[r][c];
        }
        if (hasC) {
            s += acc[r][8];
            q += acc[r][8] * acc[r][8];
        }
        sum[r] = s;
        sq[r] = q;
    }
#pragma unroll
    for (int o = 16; o; o >>= 1) {
#pragma unroll
        for (int r = 0; r < 8; r++) {
            sum[r] += __shfl_xor_sync(0xffffffffu, sum[r], o);
            sq[r] += __shfl_xor_sync(0xffffffffu, sq[r], o);
        }
    }
    {
        float4 gA = *(const float4*)(g1 + jA);
        float4 gB = *(const float4*)(g1 + jB);
        float gC = hasC ? g1[jC] : 0.f;
        float4 eA = *(const float4*)(be1 + jA);
        float4 eB = *(const float4*)(be1 + jB);
        float eC = hasC ? be1[jC] : 0.f;
        float gam[9] = {gA.x, gA.y, gA.z, gA.w, gB.x, gB.y, gB.z, gB.w, gC};
        float bet[9] = {eA.x, eA.y, eA.z, eA.w, eB.x, eB.y, eB.z, eB.w, eC};
#pragma unroll
        for (int r = 0; r < 8; r++) {
            float mu = sum[r] * (1.0f / 268.0f);
            float var = sq[r] * (1.0f / 268.0f) - mu * mu;
            float inv = rsqrtf(var + 1e-6f);
            int k = k0 + r;
            float o9[9];
#pragma unroll
            for (int c = 0; c < 9; c++)
                o9[c] = (acc[r][c] - mu) * inv * gam[c] + bet[c];
            *(float4*)&s_h1[k][jA] = make_float4(o9[0], o9[1], o9[2], o9[3]);
            *(float4*)&s_h1[k][jB] = make_float4(o9[4], o9[5], o9[6], o9[7]);
            if (hasC) s_h1[k][jC] = o9[8];
        }
    }
    __syncthreads();

    // ---- layer 2: 8 rows/warp, lane cols 4l..4l+3 (packed pairs)
    const int o0 = 4 * l;
    u64 a2p[8][2];
#pragma unroll
    for (int r = 0; r < 8; r++) { a2p[r][0] = 0ull; a2p[r][1] = 0ull; }

    for (int j4 = 0; j4 < HID / 4; j4++) {  // 67 chunks, exact
        float4 h4[8];
#pragma unroll
        for (int r = 0; r < 8; r++)
            h4[r] = *(const float4*)&s_h1[k0 + r][j4 * 4];
#pragma unroll
        for (int jj = 0; jj < 4; jj++) {
            int j = j4 * 4 + jj;
            float4 wv = *(const float4*)(w2 + j * OUTD + o0);
            u64 pw0 = pk2(wv.x, wv.y), pw1 = pk2(wv.z, wv.w);
#pragma unroll
            for (int r = 0; r < 8; r++) {
                float hv = (jj == 0) ? h4[r].x
                         : (jj == 1) ? h4[r].y
                         : (jj == 2) ? h4[r].z : h4[r].w;
                u64 hp = pk2(hv, hv);
                a2p[r][0] = f2fma(hp, pw0, a2p[r][0]);
                a2p[r][1] = f2fma(hp, pw1, a2p[r][1]);
            }
        }
    }

    float a2[8][4];
#pragma unroll
    for (int r = 0; r < 8; r++) {
        upk2(a2p[r][0], a2[r][0], a2[r][1]);
        upk2(a2p[r][1], a2[r][2], a2[r][3]);
    }
    {
        float4 bv = *(const float4*)(b2 + o0);
        float bias[4] = {bv.x, bv.y, bv.z, bv.w};
#pragma unroll
        for (int r = 0; r < 8; r++)
#pragma unroll
            for (int c = 0; c < 4; c++) a2[r][c] += bias[c];
    }
    // LN over 128 (warp-wide)
    float s2[8], q2[8];
#pragma unroll
    for (int r = 0; r < 8; r++) {
        float s = 0.f, q = 0.f;
#pragma unroll
        for (int c = 0; c < 4; c++) {
            s += a2[r][c];
            q += a2[r][c] * a2[r][c];
        }
        s2[r] = s;
        q2[r] = q;
    }
#pragma unroll
    for (int o = 16; o; o >>= 1) {
#pragma unroll
        for (int r = 0; r < 8; r++) {
            s2[r] += __shfl_xor_sync(0xffffffffu, s2[r], o);
            q2[r] += __shfl_xor_sync(0xffffffffu, q2[r], o);
        }
    }
    {
        float4 gv = *(const float4*)(g2 + o0);
        float4 ev = *(const float4*)(be2 + o0);
        float gam[4] = {gv.x, gv.y, gv.z, gv.w};
        float bet[4] = {ev.x, ev.y, ev.z, ev.w};
        float cmax[4];
#pragma unroll
        for (int c = 0; c < 4; c++) cmax[c] = -3.4e38f;
#pragma unroll
        for (int r = 0; r < 8; r++) {
            float mu = s2[r] * (1.0f / 128.0f);
            float var = q2[r] * (1.0f / 128.0f) - mu * mu;
            float inv = rsqrtf(var + 1e-6f);
#pragma unroll
            for (int c = 0; c < 4; c++) {
                float v = (a2[r][c] - mu) * inv * gam[c] + bet[c];
                cmax[c] = fmaxf(cmax[c], v);
            }
        }
#pragma unroll
        for (int c = 0; c < 4; c++) s_wmax[w][o0 + c] = cmax[c];
    }
    __syncthreads();
    if (tid < 128) {
        float m = s_wmax[0][tid];
#pragma unroll
        for (int ww = 1; ww < 4; ww++) m = fmaxf(m, s_wmax[ww][tid]);
        out[(size_t)cid * OUTD + tid] = m;
    }
}

// ---------------------------------------------------------------------------
extern "C" void kernel_launch(void* const* d_in, const int* in_sizes, int n_in,
                              void* d_out, int out_size) {
    const float* x = (const float*)d_in[0];
    const float* feat = (const float*)d_in[1];
    const int* first_idx = (const int*)d_in[2];
    const float* w1 = (const float*)d_in[3];
    const float* b1 = (const float*)d_in[4];
    const float* g1 = (const float*)d_in[5];
    const float* be1 = (const float*)d_in[6];
    const float* w2 = (const float*)d_in[7];
    const float* b2 = (const float*)d_in[8];
    const float* g2 = (const float*)d_in[9];
    const float* be2 = (const float*)d_in[10];

    float* centers = (float*)d_out;                    // [B, M, 3]
    float* out = (float*)d_out + (size_t)BB * MM * 3;  // [B, M, 128]

    int* nbr;
    cudaGetSymbolAddress((void**)&nbr, g_nbr);

    const int fps_smem = 3 * NN * (int)sizeof(float);  // 96KB coords mirror
    cudaFuncSetAttribute(fps_kernel, cudaFuncAttributeMaxDynamicSharedMemorySize,
                         fps_smem);

    fps_kernel<<<BB, 512, fps_smem>>>(x, first_idx, centers);
    bq_kernel<<<BB * MM / 4, 128>>>(x, centers, nbr);
    mlp_kernel<<<BB * MM, 128>>>(x, feat, centers, nbr, w1, b1, g1, be1, w2, b2,
                                 g2, be2, out);
}